// round 15
// baseline (speedup 1.0000x reference)
#include <cuda_runtime.h>
#include <cuda_fp16.h>
#include <math.h>

#define N_NODES 100000
#define PAD_ROWS 100096                        // 782*128 grid coverage
#define N_EDGES 600000
#define HID 128
#define SCAN_BLOCKS ((N_NODES + 255) / 256)    // 391
#define FILL_BLOCKS ((N_EDGES + 255) / 256)    // 2344
#define XS_STRIDE 68                           // uints per staged row (272B, pad for LDSM)

typedef unsigned int uint;

// ---------------- device scratch (no allocs allowed) ----------------
__device__ uint  g_Hh[(size_t)N_NODES * 64];    // H = X @ W, half2-packed
__device__ uint  g_Xh[(size_t)PAD_ROWS * 64];   // layer>=1 GEMM input, half2-packed (pad rows stay 0)
__device__ float g_dinv[N_NODES];
__device__ float g_recip[N_NODES];
__device__ int   g_cnt[N_NODES];
__device__ int   g_fill[N_NODES];
__device__ int   g_rowptr[N_NODES + 1];
__device__ int   g_csr_src[N_EDGES];
__device__ float g_csr_w[N_EDGES];
__device__ float g_gate[HID];
__device__ int   g_is64;
__device__ uint  g_Wp[3][8192];                 // W frags fp16

__device__ __forceinline__ int edge_src(const int* ei, int e, int is64) {
    return is64 ? ei[2 * e] : ei[e];
}
__device__ __forceinline__ int edge_dst(const int* ei, int e, int is64) {
    return is64 ? ei[2 * (N_EDGES + e)] : ei[N_EDGES + e];
}

// ---------------- K1: dtype detect ----------------
__global__ void detect_kernel(const int* __restrict__ ei) {
    __shared__ int any_nz;
    if (threadIdx.x == 0) any_nz = 0;
    __syncthreads();
    int local = 0;
    for (int j = threadIdx.x; j < 4096; j += 256) local |= ei[2 * j + 1];
    if (local) atomicOr(&any_nz, 1);
    __syncthreads();
    if (threadIdx.x == 0) g_is64 = (any_nz == 0) ? 1 : 0;
}

// ---------------- K2: count in-degrees ----------------
__global__ void count_kernel(const int* __restrict__ ei) {
    int e = blockIdx.x * blockDim.x + threadIdx.x;
    if (e >= N_EDGES) return;
    atomicAdd(&g_cnt[edge_dst(ei, e, g_is64)], 1);
}

// ---------------- K3: fused scan + deg + rowptr + gate + convW ----------------
__global__ void scanfuse_kernel(const float* __restrict__ t,
                                const float* __restrict__ Wg1, const float* __restrict__ bg1,
                                const float* __restrict__ Wg2, const float* __restrict__ bg2,
                                const float* __restrict__ W0, const float* __restrict__ W1,
                                const float* __restrict__ W2) {
    if (blockIdx.x >= SCAN_BLOCKS) {
        int cb = blockIdx.x - SCAN_BLOCKS;
        if (cb == 96) {
            __shared__ float h1s[HID];
            int j = threadIdx.x;
            if (j < HID) h1s[j] = tanhf(t[0] * Wg1[j] + bg1[j]);
            __syncthreads();
            if (j < HID) {
                float s = bg2[j];
#pragma unroll 8
                for (int k = 0; k < HID; k++) s += h1s[k] * Wg2[k * HID + j];
                g_gate[j] = 1.0f / (1.0f + expf(-s));
            }
            return;
        }
        int layer = cb >> 5;
        const float* W = (layer == 0) ? W0 : ((layer == 1) ? W1 : W2);
        uint* Wp = g_Wp[layer];
        int tt = (cb & 31) * 256 + threadIdx.x;
        int r = tt & 1, lane = (tt >> 1) & 31, nt = (tt >> 6) & 15, kc = tt >> 10;
        int k = kc * 16 + r * 8 + (lane & 3) * 2;
        int n = nt * 8 + (lane >> 2);
        __half2 h = __floats2half2_rn(W[k * HID + n], W[(k + 1) * HID + n]);
        Wp[tt] = *(uint*)&h;
        return;
    }

    __shared__ int sh[256];
    __shared__ int pref[256];
    int tx = threadIdx.x;
    int bid = blockIdx.x;
    int base = bid * 256;

    int local = 0;
    for (int j = tx; j < base; j += 256) local += g_cnt[j];
    pref[tx] = local;

    int i = base + tx;
    int c = (i < N_NODES) ? g_cnt[i] : 0;
    if (i < N_NODES) {
        float deg = (float)c + 1.0f;
        g_dinv[i]  = rsqrtf(deg);
        g_recip[i] = 1.0f / deg;
        g_fill[i]  = 0;
    }
    __syncthreads();
#pragma unroll
    for (int s = 128; s > 0; s >>= 1) {
        if (tx < s) pref[tx] += pref[tx + s];
        __syncthreads();
    }
    int blockoff = pref[0];

    sh[tx] = c;
    __syncthreads();
#pragma unroll
    for (int off = 1; off < 256; off <<= 1) {
        int v = (tx >= off) ? sh[tx - off] : 0;
        __syncthreads();
        sh[tx] += v;
        __syncthreads();
    }
    if (i < N_NODES) g_rowptr[i] = blockoff + sh[tx] - c;
    if (i == N_NODES - 1) g_rowptr[N_NODES] = N_EDGES;
}

// ---------------- K5: CSR fill (+ edge weights) ----------------
__global__ void fill_kernel(const int* __restrict__ ei) {
    int e = blockIdx.x * blockDim.x + threadIdx.x;
    if (e >= N_EDGES) return;
    int is64 = g_is64;
    int s = edge_src(ei, e, is64);
    int d = edge_dst(ei, e, is64);
    int pos = g_rowptr[d] + atomicAdd(&g_fill[d], 1);
    g_csr_src[pos] = s;
    g_csr_w[pos] = g_dinv[s] * g_dinv[d];
}

// ---------------- MMA / LDSM helpers ----------------
__device__ __forceinline__ void mma_f16(float* c, const uint* a, uint b0, uint b1) {
    asm volatile(
        "mma.sync.aligned.m16n8k16.row.col.f32.f16.f16.f32 "
        "{%0,%1,%2,%3}, {%4,%5,%6,%7}, {%8,%9}, {%0,%1,%2,%3};"
        : "+f"(c[0]), "+f"(c[1]), "+f"(c[2]), "+f"(c[3])
        : "r"(a[0]), "r"(a[1]), "r"(a[2]), "r"(a[3]), "r"(b0), "r"(b1));
}

__device__ __forceinline__ void ldsm_x4(uint* r, uint saddr) {
    asm volatile(
        "ldmatrix.sync.aligned.m8n8.x4.shared.b16 {%0,%1,%2,%3}, [%4];"
        : "=r"(r[0]), "=r"(r[1]), "=r"(r[2]), "=r"(r[3])
        : "r"(saddr));
}

// ---------------- GEMM: Hh = Xin @ W ----------------
// 256 threads, 128 rows/block, warp = 32 rows x 64 cols, 3 blocks/SM.
// CVT=1: Xin is fp32 x (converted during staging, bounds-checked).
// CVT=0: Xin is g_Xh half2-packed (pad rows are zero, no bounds check).
template <int CVT>
__global__ __launch_bounds__(256) void gemm_mma_kernel(
    const void* __restrict__ Xin, const uint* __restrict__ Wp,
    uint* __restrict__ Hh) {
    extern __shared__ uint smem[];
    uint* sWp = smem;                   // 8192 uints = 32KB
    uint* sX  = smem + 8192;            // 128 * 68 uints = 34816B

    int tx = threadIdx.x;
#pragma unroll
    for (int i = tx; i < 2048; i += 256)
        ((uint4*)sWp)[i] = ((const uint4*)Wp)[i];

    int rowbase = blockIdx.x * 128;
    if (CVT) {
        const float4* xf = (const float4*)Xin;
#pragma unroll
        for (int i = 0; i < 16; i++) {
            int idx = tx + i * 256;          // 0..4095 : 128 rows x 32 float4-segs
            int row = idx >> 5, seg = idx & 31;
            uint2 v = make_uint2(0, 0);
            if (rowbase + row < N_NODES) {
                float4 f = xf[(size_t)(rowbase + row) * 32 + seg];
                __half2 p0 = __floats2half2_rn(f.x, f.y);
                __half2 p1 = __floats2half2_rn(f.z, f.w);
                v = make_uint2(*(uint*)&p0, *(uint*)&p1);
            }
            *(uint2*)(sX + row * XS_STRIDE + seg * 2) = v;
        }
    } else {
        const uint4* xh = (const uint4*)Xin;
#pragma unroll
        for (int i = 0; i < 8; i++) {
            int idx = tx + i * 256;          // 0..2047 : 128 rows x 16 uint4
            int row = idx >> 4, c16 = idx & 15;
            uint4 v = xh[(size_t)rowbase * 16 + idx];
            *(uint4*)(sX + row * XS_STRIDE + c16 * 4) = v;
        }
    }
    __syncthreads();

    int warp = tx >> 5, lane = tx & 31;
    int gid = lane >> 2, tig = lane & 3;
    int colhalf = warp & 1;
    int wrow = (warp >> 1) * 32;

    int lrow = (lane & 15);
    int loff = (lane >> 4) * 16;         // bytes
    uint sxb = (uint)__cvta_generic_to_shared(sX);
    uint sa0 = sxb + ((wrow + lrow) * XS_STRIDE) * 4 + loff;
    uint sa1 = sa0 + 16 * XS_STRIDE * 4;

    float c[2][8][4];
#pragma unroll
    for (int m = 0; m < 2; m++)
#pragma unroll
        for (int j = 0; j < 8; j++)
#pragma unroll
            for (int r = 0; r < 4; r++) c[m][j][r] = 0.f;

#pragma unroll
    for (int kc = 0; kc < 8; kc++) {
        uint a0[4], a1[4];
        ldsm_x4(a0, sa0 + kc * 32);
        ldsm_x4(a1, sa1 + kc * 32);

        const uint* wp = sWp + ((kc * 16 + colhalf * 8) * 32 + lane) * 2;
#pragma unroll
        for (int j = 0; j < 8; j++) {
            uint2 w = *(const uint2*)(wp + j * 64);
            mma_f16(c[0][j], a0, w.x, w.y);
            mma_f16(c[1][j], a1, w.x, w.y);
        }
    }

    int rbase = rowbase + wrow;
#pragma unroll
    for (int m = 0; m < 2; m++) {
        int rg  = rbase + m * 16 + gid;
        int rg8 = rg + 8;
        bool w0 = rg < N_NODES, w8 = rg8 < N_NODES;
#pragma unroll
        for (int j = 0; j < 8; j++) {
            int colh = colhalf * 32 + j * 4 + tig;
            if (w0) {
                __half2 p = __floats2half2_rn(c[m][j][0], c[m][j][1]);
                Hh[(size_t)rg * 64 + colh] = *(uint*)&p;
            }
            if (w8) {
                __half2 p = __floats2half2_rn(c[m][j][2], c[m][j][3]);
                Hh[(size_t)rg8 * 64 + colh] = *(uint*)&p;
            }
        }
    }
}

// ---------------- CSR gather: half-warp per node, uint4 per lane, unroll x4 ----------------
template <int FINAL>
__global__ __launch_bounds__(256) void gather_kernel(const uint* __restrict__ Hh,
                                                     const float* __restrict__ b,
                                                     float* __restrict__ out) {
    int gtid = blockIdx.x * blockDim.x + threadIdx.x;
    int d = gtid >> 4;
    int lane = threadIdx.x & 15;
    if (d >= N_NODES) return;

    int beg = g_rowptr[d];
    int end = g_rowptr[d + 1];
    const uint4* Hr = (const uint4*)Hh;      // 16 uint4 per row

    float acc0[8], acc1[8], acc2[8], acc3[8];
    {
        float rc = g_recip[d];
        uint4 hv = Hr[(size_t)d * 16 + lane];
        const __half2* hp = (const __half2*)&hv;
#pragma unroll
        for (int q = 0; q < 4; q++) {
            float2 f = __half22float2(hp[q]);
            acc0[q * 2]     = f.x * rc;
            acc0[q * 2 + 1] = f.y * rc;
            acc1[q * 2] = 0.f; acc1[q * 2 + 1] = 0.f;
            acc2[q * 2] = 0.f; acc2[q * 2 + 1] = 0.f;
            acc3[q * 2] = 0.f; acc3[q * 2 + 1] = 0.f;
        }
    }

    int e = beg;
    for (; e + 3 < end; e += 4) {
        int s0 = g_csr_src[e],     s1 = g_csr_src[e + 1];
        int s2 = g_csr_src[e + 2], s3 = g_csr_src[e + 3];
        float w0 = g_csr_w[e],     w1 = g_csr_w[e + 1];
        float w2 = g_csr_w[e + 2], w3 = g_csr_w[e + 3];
        uint4 r0 = Hr[(size_t)s0 * 16 + lane];
        uint4 r1 = Hr[(size_t)s1 * 16 + lane];
        uint4 r2 = Hr[(size_t)s2 * 16 + lane];
        uint4 r3 = Hr[(size_t)s3 * 16 + lane];
        const __half2* q0 = (const __half2*)&r0;
        const __half2* q1 = (const __half2*)&r1;
        const __half2* q2 = (const __half2*)&r2;
        const __half2* q3 = (const __half2*)&r3;
#pragma unroll
        for (int q = 0; q < 4; q++) {
            float2 f0 = __half22float2(q0[q]);
            float2 f1 = __half22float2(q1[q]);
            float2 f2 = __half22float2(q2[q]);
            float2 f3 = __half22float2(q3[q]);
            acc0[q * 2]     += f0.x * w0; acc0[q * 2 + 1] += f0.y * w0;
            acc1[q * 2]     += f1.x * w1; acc1[q * 2 + 1] += f1.y * w1;
            acc2[q * 2]     += f2.x * w2; acc2[q * 2 + 1] += f2.y * w2;
            acc3[q * 2]     += f3.x * w3; acc3[q * 2 + 1] += f3.y * w3;
        }
    }
    for (; e < end; e++) {
        int s0 = g_csr_src[e];
        float w0 = g_csr_w[e];
        uint4 r0 = Hr[(size_t)s0 * 16 + lane];
        const __half2* q0 = (const __half2*)&r0;
#pragma unroll
        for (int q = 0; q < 4; q++) {
            float2 f0 = __half22float2(q0[q]);
            acc0[q * 2]     += f0.x * w0;
            acc0[q * 2 + 1] += f0.y * w0;
        }
    }

    float4 bv0 = ((const float4*)b)[lane * 2];
    float4 bv1 = ((const float4*)b)[lane * 2 + 1];
    float4 g0  = ((const float4*)g_gate)[lane * 2];
    float4 g1  = ((const float4*)g_gate)[lane * 2 + 1];
    float bb[8] = {bv0.x, bv0.y, bv0.z, bv0.w, bv1.x, bv1.y, bv1.z, bv1.w};
    float gg[8] = {g0.x,  g0.y,  g0.z,  g0.w,  g1.x,  g1.y,  g1.z,  g1.w};

    float o[8];
#pragma unroll
    for (int q = 0; q < 8; q++)
        o[q] = fmaxf((acc0[q] + acc1[q]) + (acc2[q] + acc3[q]) + bb[q], 0.f) * gg[q];

    if (FINAL) {
        float4* orow = (float4*)(out + (size_t)d * HID);
        orow[lane * 2]     = make_float4(o[0], o[1], o[2], o[3]);
        orow[lane * 2 + 1] = make_float4(o[4], o[5], o[6], o[7]);
    } else {
        __half2 p0 = __floats2half2_rn(o[0], o[1]);
        __half2 p1 = __floats2half2_rn(o[2], o[3]);
        __half2 p2 = __floats2half2_rn(o[4], o[5]);
        __half2 p3 = __floats2half2_rn(o[6], o[7]);
        ((uint4*)g_Xh)[(size_t)d * 16 + lane] =
            make_uint4(*(uint*)&p0, *(uint*)&p1, *(uint*)&p2, *(uint*)&p3);
    }
}

// ---------------- launch ----------------
extern "C" void kernel_launch(void* const* d_in, const int* in_sizes, int n_in,
                              void* d_out, int out_size) {
    const float* x   = (const float*)d_in[0];
    const int*   ei  = (const int*)d_in[1];
    const float* ts  = (const float*)d_in[2];
    const float* W0  = (const float*)d_in[3];
    const float* b0  = (const float*)d_in[4];
    const float* W1  = (const float*)d_in[5];
    const float* b1  = (const float*)d_in[6];
    const float* W2  = (const float*)d_in[7];
    const float* b2  = (const float*)d_in[8];
    const float* Wg1 = (const float*)d_in[9];
    const float* bg1 = (const float*)d_in[10];
    const float* Wg2 = (const float*)d_in[11];
    const float* bg2 = (const float*)d_in[12];
    float* out = (float*)d_out;

    const int SMEM = (8192 + 128 * XS_STRIDE) * 4;   // 32KB + 34KB = 67584B
    cudaFuncSetAttribute(gemm_mma_kernel<0>, cudaFuncAttributeMaxDynamicSharedMemorySize, SMEM);
    cudaFuncSetAttribute(gemm_mma_kernel<1>, cudaFuncAttributeMaxDynamicSharedMemorySize, SMEM);

    uint *Hh, *Xh, *Wp;
    int  *cnt;
    cudaGetSymbolAddress((void**)&Hh,  g_Hh);
    cudaGetSymbolAddress((void**)&Xh,  g_Xh);
    cudaGetSymbolAddress((void**)&Wp,  g_Wp);
    cudaGetSymbolAddress((void**)&cnt, g_cnt);

    const int gemm_blocks = (N_NODES + 127) / 128;         // 782
    const int gath_blocks = (N_NODES * 16 + 255) / 256;    // 6250

    cudaMemsetAsync(cnt, 0, N_NODES * sizeof(int), 0);
    detect_kernel<<<1, 256>>>(ei);                                           // #1
    count_kernel<<<FILL_BLOCKS, 256>>>(ei);                                  // #2
    scanfuse_kernel<<<SCAN_BLOCKS + 97, 256>>>(ts, Wg1, bg1, Wg2, bg2,
                                               W0, W1, W2);                  // #3
    gemm_mma_kernel<1><<<gemm_blocks, 256, SMEM>>>(x, Wp, Hh);               // #4 (profiled)
    fill_kernel<<<FILL_BLOCKS, 256>>>(ei);                                   // #5
    gather_kernel<0><<<gath_blocks, 256>>>(Hh, b0, out);
    gemm_mma_kernel<0><<<gemm_blocks, 256, SMEM>>>(Xh, Wp + 8192, Hh);
    gather_kernel<0><<<gath_blocks, 256>>>(Hh, b1, out);
    gemm_mma_kernel<0><<<gemm_blocks, 256, SMEM>>>(Xh, Wp + 16384, Hh);
    gather_kernel<1><<<gath_blocks, 256>>>(Hh, b2, out);
}

// round 16
// speedup vs baseline: 1.1369x; 1.1369x over previous
#include <cuda_runtime.h>
#include <cuda_fp16.h>
#include <math.h>

#define N_NODES 100000
#define PAD_ROWS 100096                        // 391*256 grid coverage
#define N_EDGES 600000
#define HID 128
#define SCAN_BLOCKS ((N_NODES + 255) / 256)    // 391
#define FILL_BLOCKS ((N_EDGES + 255) / 256)    // 2344
#define XS_STRIDE 68                           // uints per staged row (272B, pad for LDSM)

typedef unsigned int uint;

// ---------------- device scratch (no allocs allowed) ----------------
__device__ uint  g_Hh[(size_t)N_NODES * 64];    // H = X @ W, half2-packed
__device__ uint  g_Xh[(size_t)PAD_ROWS * 64];   // layer>=1 GEMM input, half2-packed (pad rows stay 0)
__device__ float g_dinv[N_NODES];
__device__ float g_recip[N_NODES];
__device__ int   g_cnt[N_NODES];
__device__ int   g_fill[N_NODES];
__device__ int   g_rowptr[N_NODES + 1];
__device__ int   g_csr_src[N_EDGES];
__device__ float g_csr_w[N_EDGES];
__device__ float g_gate[HID];
__device__ int   g_is64;
__device__ uint  g_Wp[3][8192];                 // W frags fp16

__device__ __forceinline__ int edge_src(const int* ei, int e, int is64) {
    return is64 ? ei[2 * e] : ei[e];
}
__device__ __forceinline__ int edge_dst(const int* ei, int e, int is64) {
    return is64 ? ei[2 * (N_EDGES + e)] : ei[N_EDGES + e];
}

// ---------------- K1: dtype detect ----------------
__global__ void detect_kernel(const int* __restrict__ ei) {
    __shared__ int any_nz;
    if (threadIdx.x == 0) any_nz = 0;
    __syncthreads();
    int local = 0;
    for (int j = threadIdx.x; j < 4096; j += 256) local |= ei[2 * j + 1];
    if (local) atomicOr(&any_nz, 1);
    __syncthreads();
    if (threadIdx.x == 0) g_is64 = (any_nz == 0) ? 1 : 0;
}

// ---------------- K2: count in-degrees ----------------
__global__ void count_kernel(const int* __restrict__ ei) {
    int e = blockIdx.x * blockDim.x + threadIdx.x;
    if (e >= N_EDGES) return;
    atomicAdd(&g_cnt[edge_dst(ei, e, g_is64)], 1);
}

// ---------------- K3: fused scan + deg + rowptr + gate + convW ----------------
__global__ void scanfuse_kernel(const float* __restrict__ t,
                                const float* __restrict__ Wg1, const float* __restrict__ bg1,
                                const float* __restrict__ Wg2, const float* __restrict__ bg2,
                                const float* __restrict__ W0, const float* __restrict__ W1,
                                const float* __restrict__ W2) {
    if (blockIdx.x >= SCAN_BLOCKS) {
        int cb = blockIdx.x - SCAN_BLOCKS;
        if (cb == 96) {
            __shared__ float h1s[HID];
            int j = threadIdx.x;
            if (j < HID) h1s[j] = tanhf(t[0] * Wg1[j] + bg1[j]);
            __syncthreads();
            if (j < HID) {
                float s = bg2[j];
#pragma unroll 8
                for (int k = 0; k < HID; k++) s += h1s[k] * Wg2[k * HID + j];
                g_gate[j] = 1.0f / (1.0f + expf(-s));
            }
            return;
        }
        int layer = cb >> 5;
        const float* W = (layer == 0) ? W0 : ((layer == 1) ? W1 : W2);
        uint* Wp = g_Wp[layer];
        int tt = (cb & 31) * 256 + threadIdx.x;
        int r = tt & 1, lane = (tt >> 1) & 31, nt = (tt >> 6) & 15, kc = tt >> 10;
        int k = kc * 16 + r * 8 + (lane & 3) * 2;
        int n = nt * 8 + (lane >> 2);
        __half2 h = __floats2half2_rn(W[k * HID + n], W[(k + 1) * HID + n]);
        Wp[tt] = *(uint*)&h;
        return;
    }

    __shared__ int sh[256];
    __shared__ int pref[256];
    int tx = threadIdx.x;
    int bid = blockIdx.x;
    int base = bid * 256;

    int local = 0;
    for (int j = tx; j < base; j += 256) local += g_cnt[j];
    pref[tx] = local;

    int i = base + tx;
    int c = (i < N_NODES) ? g_cnt[i] : 0;
    if (i < N_NODES) {
        float deg = (float)c + 1.0f;
        g_dinv[i]  = rsqrtf(deg);
        g_recip[i] = 1.0f / deg;
        g_fill[i]  = 0;
    }
    __syncthreads();
#pragma unroll
    for (int s = 128; s > 0; s >>= 1) {
        if (tx < s) pref[tx] += pref[tx + s];
        __syncthreads();
    }
    int blockoff = pref[0];

    sh[tx] = c;
    __syncthreads();
#pragma unroll
    for (int off = 1; off < 256; off <<= 1) {
        int v = (tx >= off) ? sh[tx - off] : 0;
        __syncthreads();
        sh[tx] += v;
        __syncthreads();
    }
    if (i < N_NODES) g_rowptr[i] = blockoff + sh[tx] - c;
    if (i == N_NODES - 1) g_rowptr[N_NODES] = N_EDGES;
}

// ---------------- K5: CSR fill (+ edge weights) ----------------
__global__ void fill_kernel(const int* __restrict__ ei) {
    int e = blockIdx.x * blockDim.x + threadIdx.x;
    if (e >= N_EDGES) return;
    int is64 = g_is64;
    int s = edge_src(ei, e, is64);
    int d = edge_dst(ei, e, is64);
    int pos = g_rowptr[d] + atomicAdd(&g_fill[d], 1);
    g_csr_src[pos] = s;
    g_csr_w[pos] = g_dinv[s] * g_dinv[d];
}

// ---------------- MMA / LDSM helpers ----------------
__device__ __forceinline__ void mma_f16(float* c, const uint* a, uint b0, uint b1) {
    asm volatile(
        "mma.sync.aligned.m16n8k16.row.col.f32.f16.f16.f32 "
        "{%0,%1,%2,%3}, {%4,%5,%6,%7}, {%8,%9}, {%0,%1,%2,%3};"
        : "+f"(c[0]), "+f"(c[1]), "+f"(c[2]), "+f"(c[3])
        : "r"(a[0]), "r"(a[1]), "r"(a[2]), "r"(a[3]), "r"(b0), "r"(b1));
}

__device__ __forceinline__ void ldsm_x4(uint* r, uint saddr) {
    asm volatile(
        "ldmatrix.sync.aligned.m8n8.x4.shared.b16 {%0,%1,%2,%3}, [%4];"
        : "=r"(r[0]), "=r"(r[1]), "=r"(r[2]), "=r"(r[3])
        : "r"(saddr));
}

// ---------------- GEMM: Hh = Xin @ W  (512 thr, 256 rows/block, warp = 32x64) ----------------
// CVT=1: Xin is fp32 x, converted to fp16 during coalesced smem staging (bounds-checked).
// CVT=0: Xin is g_Xh half2-packed (pad rows are zero, no bounds check).
template <int CVT>
__global__ __launch_bounds__(512) void gemm_mma_kernel(
    const void* __restrict__ Xin, const uint* __restrict__ Wp,
    uint* __restrict__ Hh) {
    extern __shared__ uint smem[];
    uint* sWp = smem;                   // 8192 uints = 32KB
    uint* sX  = smem + 8192;            // 256 * 68 uints = 69632B

    int tx = threadIdx.x;
#pragma unroll
    for (int i = tx; i < 2048; i += 512)
        ((uint4*)sWp)[i] = ((const uint4*)Wp)[i];

    int rowbase = blockIdx.x * 256;
    if (CVT) {
        const float4* xf = (const float4*)Xin;
#pragma unroll
        for (int i = 0; i < 16; i++) {
            int idx = tx + i * 512;          // 0..8191 : 256 rows x 32 float4-segs
            int row = idx >> 5, seg = idx & 31;
            uint2 v = make_uint2(0, 0);
            if (rowbase + row < N_NODES) {
                float4 f = xf[(size_t)(rowbase + row) * 32 + seg];
                __half2 p0 = __floats2half2_rn(f.x, f.y);
                __half2 p1 = __floats2half2_rn(f.z, f.w);
                v = make_uint2(*(uint*)&p0, *(uint*)&p1);
            }
            *(uint2*)(sX + row * XS_STRIDE + seg * 2) = v;
        }
    } else {
        const uint4* xh = (const uint4*)Xin;
#pragma unroll
        for (int i = 0; i < 8; i++) {
            int idx = tx + i * 512;          // 0..4095 : 256 rows x 16 uint4
            int row = idx >> 4, c16 = idx & 15;
            uint4 v = xh[(size_t)rowbase * 16 + idx];
            *(uint4*)(sX + row * XS_STRIDE + c16 * 4) = v;
        }
    }
    __syncthreads();

    int warp = tx >> 5, lane = tx & 31;
    int gid = lane >> 2, tig = lane & 3;
    int colhalf = warp & 1;
    int wrow = (warp >> 1) * 32;         // warp = 32 rows x 64 cols

    int lrow = (lane & 15);
    int loff = (lane >> 4) * 16;         // bytes
    uint sxb = (uint)__cvta_generic_to_shared(sX);
    uint sa0 = sxb + ((wrow + lrow) * XS_STRIDE) * 4 + loff;
    uint sa1 = sa0 + 16 * XS_STRIDE * 4;

    float c[2][8][4];
#pragma unroll
    for (int m = 0; m < 2; m++)
#pragma unroll
        for (int j = 0; j < 8; j++)
#pragma unroll
            for (int r = 0; r < 4; r++) c[m][j][r] = 0.f;

#pragma unroll
    for (int kc = 0; kc < 8; kc++) {
        uint a0[4], a1[4];
        ldsm_x4(a0, sa0 + kc * 32);
        ldsm_x4(a1, sa1 + kc * 32);

        const uint* wp = sWp + ((kc * 16 + colhalf * 8) * 32 + lane) * 2;
#pragma unroll
        for (int j = 0; j < 8; j++) {
            uint2 w = *(const uint2*)(wp + j * 64);
            mma_f16(c[0][j], a0, w.x, w.y);
            mma_f16(c[1][j], a1, w.x, w.y);
        }
    }

    int rbase = rowbase + wrow;
#pragma unroll
    for (int m = 0; m < 2; m++) {
        int rg  = rbase + m * 16 + gid;
        int rg8 = rg + 8;
        bool w0 = rg < N_NODES, w8 = rg8 < N_NODES;
#pragma unroll
        for (int j = 0; j < 8; j++) {
            int colh = colhalf * 32 + j * 4 + tig;
            if (w0) {
                __half2 p = __floats2half2_rn(c[m][j][0], c[m][j][1]);
                Hh[(size_t)rg * 64 + colh] = *(uint*)&p;
            }
            if (w8) {
                __half2 p = __floats2half2_rn(c[m][j][2], c[m][j][3]);
                Hh[(size_t)rg8 * 64 + colh] = *(uint*)&p;
            }
        }
    }
}

// ---------------- CSR gather: half-warp per node, uint4 per lane, unroll x2 ----------------
template <int FINAL>
__global__ __launch_bounds__(256) void gather_kernel(const uint* __restrict__ Hh,
                                                     const float* __restrict__ b,
                                                     float* __restrict__ out) {
    int gtid = blockIdx.x * blockDim.x + threadIdx.x;
    int d = gtid >> 4;
    int lane = threadIdx.x & 15;
    if (d >= N_NODES) return;

    int beg = g_rowptr[d];
    int end = g_rowptr[d + 1];
    const uint4* Hr = (const uint4*)Hh;      // 16 uint4 per row

    float acc0[8], acc1[8];
    {
        float rc = g_recip[d];
        uint4 hv = Hr[(size_t)d * 16 + lane];
        const __half2* hp = (const __half2*)&hv;
#pragma unroll
        for (int q = 0; q < 4; q++) {
            float2 f = __half22float2(hp[q]);
            acc0[q * 2]     = f.x * rc;
            acc0[q * 2 + 1] = f.y * rc;
            acc1[q * 2]     = 0.f;
            acc1[q * 2 + 1] = 0.f;
        }
    }

    int e = beg;
    for (; e + 1 < end; e += 2) {
        int s0 = g_csr_src[e];
        int s1 = g_csr_src[e + 1];
        float w0 = g_csr_w[e];
        float w1 = g_csr_w[e + 1];
        uint4 r0 = Hr[(size_t)s0 * 16 + lane];
        uint4 r1 = Hr[(size_t)s1 * 16 + lane];
        const __half2* q0 = (const __half2*)&r0;
        const __half2* q1 = (const __half2*)&r1;
#pragma unroll
        for (int q = 0; q < 4; q++) {
            float2 f0 = __half22float2(q0[q]);
            float2 f1 = __half22float2(q1[q]);
            acc0[q * 2]     += f0.x * w0;
            acc0[q * 2 + 1] += f0.y * w0;
            acc1[q * 2]     += f1.x * w1;
            acc1[q * 2 + 1] += f1.y * w1;
        }
    }
    if (e < end) {
        int s0 = g_csr_src[e];
        float w0 = g_csr_w[e];
        uint4 r0 = Hr[(size_t)s0 * 16 + lane];
        const __half2* q0 = (const __half2*)&r0;
#pragma unroll
        for (int q = 0; q < 4; q++) {
            float2 f0 = __half22float2(q0[q]);
            acc0[q * 2]     += f0.x * w0;
            acc0[q * 2 + 1] += f0.y * w0;
        }
    }

    float4 bv0 = ((const float4*)b)[lane * 2];
    float4 bv1 = ((const float4*)b)[lane * 2 + 1];
    float4 g0  = ((const float4*)g_gate)[lane * 2];
    float4 g1  = ((const float4*)g_gate)[lane * 2 + 1];
    float bb[8] = {bv0.x, bv0.y, bv0.z, bv0.w, bv1.x, bv1.y, bv1.z, bv1.w};
    float gg[8] = {g0.x,  g0.y,  g0.z,  g0.w,  g1.x,  g1.y,  g1.z,  g1.w};

    float o[8];
#pragma unroll
    for (int q = 0; q < 8; q++)
        o[q] = fmaxf(acc0[q] + acc1[q] + bb[q], 0.f) * gg[q];

    if (FINAL) {
        float4* orow = (float4*)(out + (size_t)d * HID);
        orow[lane * 2]     = make_float4(o[0], o[1], o[2], o[3]);
        orow[lane * 2 + 1] = make_float4(o[4], o[5], o[6], o[7]);
    } else {
        __half2 p0 = __floats2half2_rn(o[0], o[1]);
        __half2 p1 = __floats2half2_rn(o[2], o[3]);
        __half2 p2 = __floats2half2_rn(o[4], o[5]);
        __half2 p3 = __floats2half2_rn(o[6], o[7]);
        ((uint4*)g_Xh)[(size_t)d * 16 + lane] =
            make_uint4(*(uint*)&p0, *(uint*)&p1, *(uint*)&p2, *(uint*)&p3);
    }
}

// ---------------- launch ----------------
extern "C" void kernel_launch(void* const* d_in, const int* in_sizes, int n_in,
                              void* d_out, int out_size) {
    const float* x   = (const float*)d_in[0];
    const int*   ei  = (const int*)d_in[1];
    const float* ts  = (const float*)d_in[2];
    const float* W0  = (const float*)d_in[3];
    const float* b0  = (const float*)d_in[4];
    const float* W1  = (const float*)d_in[5];
    const float* b1  = (const float*)d_in[6];
    const float* W2  = (const float*)d_in[7];
    const float* b2  = (const float*)d_in[8];
    const float* Wg1 = (const float*)d_in[9];
    const float* bg1 = (const float*)d_in[10];
    const float* Wg2 = (const float*)d_in[11];
    const float* bg2 = (const float*)d_in[12];
    float* out = (float*)d_out;

    const int SMEM = (8192 + 256 * XS_STRIDE) * 4;   // 32KB + 68KB = 102400B
    cudaFuncSetAttribute(gemm_mma_kernel<0>, cudaFuncAttributeMaxDynamicSharedMemorySize, SMEM);
    cudaFuncSetAttribute(gemm_mma_kernel<1>, cudaFuncAttributeMaxDynamicSharedMemorySize, SMEM);

    uint *Hh, *Xh, *Wp;
    int  *cnt;
    cudaGetSymbolAddress((void**)&Hh,  g_Hh);
    cudaGetSymbolAddress((void**)&Xh,  g_Xh);
    cudaGetSymbolAddress((void**)&Wp,  g_Wp);
    cudaGetSymbolAddress((void**)&cnt, g_cnt);

    const int gemm_blocks = (N_NODES + 255) / 256;         // 391
    const int gath_blocks = (N_NODES * 16 + 255) / 256;    // 6250

    cudaMemsetAsync(cnt, 0, N_NODES * sizeof(int), 0);
    detect_kernel<<<1, 256>>>(ei);                                           // #1
    count_kernel<<<FILL_BLOCKS, 256>>>(ei);                                  // #2
    scanfuse_kernel<<<SCAN_BLOCKS + 97, 256>>>(ts, Wg1, bg1, Wg2, bg2,
                                               W0, W1, W2);                  // #3
    gemm_mma_kernel<1><<<gemm_blocks, 512, SMEM>>>(x, Wp, Hh);               // #4 (profiled)
    fill_kernel<<<FILL_BLOCKS, 256>>>(ei);                                   // #5
    gather_kernel<0><<<gath_blocks, 256>>>(Hh, b0, out);
    gemm_mma_kernel<0><<<gemm_blocks, 512, SMEM>>>(Xh, Wp + 8192, Hh);
    gather_kernel<0><<<gath_blocks, 256>>>(Hh, b1, out);
    gemm_mma_kernel<0><<<gemm_blocks, 512, SMEM>>>(Xh, Wp + 16384, Hh);
    gather_kernel<1><<<gath_blocks, 256>>>(Hh, b2, out);
}